// round 8
// baseline (speedup 1.0000x reference)
#include <cuda_runtime.h>
#include <cstdint>

#define N_FINE    200000
#define N_COARSE  50000
#define ROW_F4    128      // (2 groups * 128 ch * 2 cplx) floats / 4 = 128 float4 per row
#define BIN_SHIFT 9        // 512 coarse rows per bin = 1 MB of x per bin
#define NBINS     ((N_COARSE + (1 << BIN_SHIFT) - 1) >> BIN_SHIFT)   // 98

// ---------- device scratch (no runtime allocation allowed) ----------
__device__ int g_unpool_map[N_FINE];   // zero-init matches jnp.zeros; scatter idempotent

struct __align__(16) EdgeRec { int src; int dst; float c; float s; };
__device__ EdgeRec g_edge[N_FINE];     // 3.2 MB, sorted into src-bin order

__device__ int g_binCnt[NBINS];
__device__ int g_binOff[NBINS];
__device__ int g_binCur[NBINS];

// ---------- phase 0: reset counters (graph replays reuse state) ----------
__global__ void zero_kernel() {
    int i = threadIdx.x;
    if (i < NBINS) { g_binCnt[i] = 0; g_binCur[i] = 0; }
}

// ---------- phase 1: inverse permutation ----------
__global__ void build_map_kernel(const int* __restrict__ nodes) {
    int i = blockIdx.x * blockDim.x + threadIdx.x;
    if (i < N_COARSE) g_unpool_map[nodes[i]] = i;
}

// ---------- phase 2: histogram of edges per src-bin ----------
__global__ void hist_kernel(const int* __restrict__ edge_src) {
    int e = blockIdx.x * blockDim.x + threadIdx.x;
    if (e < N_FINE) {
        int src = g_unpool_map[edge_src[e]];
        atomicAdd(&g_binCnt[src >> BIN_SHIFT], 1);
    }
}

// ---------- phase 3: exclusive scan over NBINS (single block) ----------
__global__ void scan_kernel() {
    __shared__ int sh[128];
    int i = threadIdx.x;
    int v = (i < NBINS) ? g_binCnt[i] : 0;
    sh[i] = v;
    __syncthreads();
    #pragma unroll
    for (int d = 1; d < 128; d <<= 1) {
        int t = (i >= d) ? sh[i - d] : 0;
        __syncthreads();
        sh[i] += t;
        __syncthreads();
    }
    if (i < NBINS) g_binOff[i] = sh[i] - v;   // exclusive
}

// ---------- phase 4: place resolved edge records into bin order ----------
// Within-bin order is nondeterministic (atomic grab) but the final output is
// order-invariant: every edge owns a distinct dst row.
__global__ void place_kernel(const int*    __restrict__ edge_src,
                             const int*    __restrict__ edge_dst,
                             const float2* __restrict__ conn) {
    int e = blockIdx.x * blockDim.x + threadIdx.x;
    if (e < N_FINE) {
        int src = g_unpool_map[edge_src[e]];
        int bin = src >> BIN_SHIFT;
        int pos = g_binOff[bin] + atomicAdd(&g_binCur[bin], 1);
        EdgeRec r;
        r.src = src;
        r.dst = edge_dst[e];
        float2 cs = conn[e];
        r.c = cs.x;
        r.s = cs.y;
        g_edge[pos] = r;
    }
}

// ---------- phase 5: gather row, rotate group 1, scatter ----------
// One warp per edge; edges arrive in src-bin order, so the x rows live in a
// rotating ~1-2 MB L2-resident slice and each row's ~4 gathers hit cache.
// Thread j handles float4s j, j+32 (group 0: copy) and j+64, j+96 (group 1:
// multiply by conj(c,s)). Streaming stores keep the touch-once 410 MB output
// from displacing the slice.
__global__ void __launch_bounds__(256)
unpool_kernel(const float4* __restrict__ x, float4* __restrict__ out) {
    int t = blockIdx.x * blockDim.x + threadIdx.x;
    int e = t >> 5;        // edge index — uniform across the warp
    int j = t & 31;        // float4 lane
    if (e >= N_FINE) return;

    // Single warp-uniform 16-byte load for all per-edge metadata.
    int4 raw = *reinterpret_cast<const int4*>(&g_edge[e]);
    int   src = raw.x;
    int   dst = raw.y;
    float c   = __int_as_float(raw.z);
    float s   = __int_as_float(raw.w);

    const float4* xr = x + (size_t)src * ROW_F4;
    float4 v0 = __ldg(xr + j);          // group 0
    float4 v1 = __ldg(xr + j + 32);     // group 0
    float4 v2 = __ldg(xr + j + 64);     // group 1
    float4 v3 = __ldg(xr + j + 96);     // group 1

    // (re + i*im) * (c - i*s)
    float4 r2, r3;
    r2.x = fmaf(v2.x, c,  v2.y * s);
    r2.y = fmaf(v2.y, c, -v2.x * s);
    r2.z = fmaf(v2.z, c,  v2.w * s);
    r2.w = fmaf(v2.w, c, -v2.z * s);
    r3.x = fmaf(v3.x, c,  v3.y * s);
    r3.y = fmaf(v3.y, c, -v3.x * s);
    r3.z = fmaf(v3.z, c,  v3.w * s);
    r3.w = fmaf(v3.w, c, -v3.z * s);

    float4* o = out + (size_t)dst * ROW_F4;
    __stcs(o + j,      v0);
    __stcs(o + j + 32, v1);
    __stcs(o + j + 64, r2);
    __stcs(o + j + 96, r3);
}

extern "C" void kernel_launch(void* const* d_in, const int* in_sizes, int n_in,
                              void* d_out, int out_size) {
    // metadata order: x, unpool_connection, unpool_nodes, unpool_edges, num_nodes
    const float4* x     = (const float4*)d_in[0];
    const float2* conn  = (const float2*)d_in[1];
    const int*    nodes = (const int*)d_in[2];
    const int*    edges = (const int*)d_in[3];   // [2, N_FINE]: row0=src, row1=dst
    float4*       out   = (float4*)d_out;

    (void)in_sizes; (void)n_in; (void)out_size;

    zero_kernel<<<1, 128>>>();
    build_map_kernel<<<(N_COARSE + 255) / 256, 256>>>(nodes);
    hist_kernel<<<(N_FINE + 255) / 256, 256>>>(edges);
    scan_kernel<<<1, 128>>>();
    place_kernel<<<(N_FINE + 255) / 256, 256>>>(edges, edges + N_FINE, conn);

    const long long total = (long long)N_FINE * 32;   // 6.4M threads
    unpool_kernel<<<(unsigned)((total + 255) / 256), 256>>>(x, out);
}

// round 13
// speedup vs baseline: 1.5871x; 1.5871x over previous
#include <cuda_runtime.h>
#include <cstdint>

#define N_FINE   200000
#define N_COARSE 50000
#define ROW_F4   128   // (2 groups * 128 ch * 2 cplx) floats / 4 = 128 float4 per row

// ---------- device scratch (no runtime allocation allowed) ----------
// Inverse permutation: zero-init matches jnp.zeros; scatter is idempotent
// across graph replays -> deterministic.
__device__ int g_unpool_map[N_FINE];

// ---------- phase 1 (only prep kernel): inverse permutation ----------
__global__ void build_map_kernel(const int* __restrict__ nodes) {
    int i = blockIdx.x * blockDim.x + threadIdx.x;
    if (i < N_COARSE) g_unpool_map[nodes[i]] = i;
}

// ---------- phase 2: resolve + gather + rotate + scatter, fused ----------
// One warp per edge. Edge metadata is resolved inline by two lanes
// (lane0: edge_src -> map -> coarse row; lane1: dst + cos/sin) and
// broadcast via shuffles — no intermediate EdgeRec array, no second prep
// kernel. e is warp-uniform, so the early exit never splits a warp and the
// shuffles are always fully converged. Thread j handles float4s j, j+32
// (group 0: copy) and j+64, j+96 (group 1: multiply by conj(c,s)) -> MLP=4
// coalesced loads. Streaming stores keep the touch-once 410 MB output from
// thrashing the x working set in L2.
__global__ void __launch_bounds__(256)
unpool_kernel(const float4* __restrict__ x,
              const float2* __restrict__ conn,
              const int*    __restrict__ edge_src,
              const int*    __restrict__ edge_dst,
              float4*       __restrict__ out) {
    int t = blockIdx.x * blockDim.x + threadIdx.x;
    int e = t >> 5;        // edge index — uniform across the warp
    int j = t & 31;        // float4 lane
    if (e >= N_FINE) return;

    // Per-warp metadata, loaded by 2 lanes in parallel then broadcast.
    int   src = 0, dst = 0;
    float c = 0.f, s = 0.f;
    if (j == 0) src = g_unpool_map[edge_src[e]];        // 2-deep chain, lane 0
    if (j == 1) { dst = edge_dst[e];
                  float2 cs = conn[e]; c = cs.x; s = cs.y; }
    src = __shfl_sync(0xffffffffu, src, 0);
    dst = __shfl_sync(0xffffffffu, dst, 1);
    c   = __shfl_sync(0xffffffffu, c,   1);
    s   = __shfl_sync(0xffffffffu, s,   1);

    const float4* xr = x + (size_t)src * ROW_F4;
    float4 v0 = __ldg(xr + j);          // group 0
    float4 v1 = __ldg(xr + j + 32);     // group 0
    float4 v2 = __ldg(xr + j + 64);     // group 1
    float4 v3 = __ldg(xr + j + 96);     // group 1

    // (re + i*im) * (c - i*s)
    float4 r2, r3;
    r2.x = fmaf(v2.x, c,  v2.y * s);
    r2.y = fmaf(v2.y, c, -v2.x * s);
    r2.z = fmaf(v2.z, c,  v2.w * s);
    r2.w = fmaf(v2.w, c, -v2.z * s);
    r3.x = fmaf(v3.x, c,  v3.y * s);
    r3.y = fmaf(v3.y, c, -v3.x * s);
    r3.z = fmaf(v3.z, c,  v3.w * s);
    r3.w = fmaf(v3.w, c, -v3.z * s);

    float4* o = out + (size_t)dst * ROW_F4;
    __stcs(o + j,      v0);
    __stcs(o + j + 32, v1);
    __stcs(o + j + 64, r2);
    __stcs(o + j + 96, r3);
}

extern "C" void kernel_launch(void* const* d_in, const int* in_sizes, int n_in,
                              void* d_out, int out_size) {
    // metadata order: x, unpool_connection, unpool_nodes, unpool_edges, num_nodes
    const float4* x     = (const float4*)d_in[0];
    const float2* conn  = (const float2*)d_in[1];
    const int*    nodes = (const int*)d_in[2];
    const int*    edges = (const int*)d_in[3];   // [2, N_FINE]: row0=src, row1=dst
    float4*       out   = (float4*)d_out;

    (void)in_sizes; (void)n_in; (void)out_size;

    build_map_kernel<<<(N_COARSE + 255) / 256, 256>>>(nodes);

    const long long total = (long long)N_FINE * 32;   // 6.4M threads
    unpool_kernel<<<(unsigned)((total + 255) / 256), 256>>>(
        x, conn, edges, edges + N_FINE, out);
}

// round 14
// speedup vs baseline: 1.5928x; 1.0036x over previous
#include <cuda_runtime.h>
#include <cstdint>

#define N_FINE   200000
#define N_COARSE 50000
#define ROW_F4   128   // (2 groups * 128 ch * 2 cplx) floats / 4 = 128 float4 per row

// ---------- device scratch (no runtime allocation allowed) ----------
// Inverse permutation: zero-init matches jnp.zeros; scatter is idempotent
// across graph replays -> deterministic.
__device__ int g_unpool_map[N_FINE];

// ---------- phase 1 (only prep kernel): inverse permutation ----------
__global__ void build_map_kernel(const int* __restrict__ nodes) {
    int i = blockIdx.x * blockDim.x + threadIdx.x;
    if (i < N_COARSE) g_unpool_map[nodes[i]] = i;
}

// ---------- phase 2: resolve + gather + rotate + scatter, fused ----------
// TWO edges per warp. Metadata resolved inline by four lanes (0: src0,
// 1: dst0+cs0, 2: src1, 3: dst1+cs1) and broadcast via shuffles. All EIGHT
// row loads issue back-to-back before any compute -> doubles the
// read-outstanding bytes per warp lifetime (the duty-cycle fix for the 76%
// DRAM plateau). Thread j covers float4s {j, j+32} (group 0: copy) and
// {j+64, j+96} (group 1: multiply by conj(c,s)) of each edge's row.
// Streaming stores keep the touch-once 410 MB output from thrashing x in L2.
// N_FINE is even, so a warp either has both edges or none.
__global__ void __launch_bounds__(256)
unpool_kernel(const float4* __restrict__ x,
              const float2* __restrict__ conn,
              const int*    __restrict__ edge_src,
              const int*    __restrict__ edge_dst,
              float4*       __restrict__ out) {
    int t  = blockIdx.x * blockDim.x + threadIdx.x;
    int e0 = (t >> 5) * 2;     // first edge of this warp — warp-uniform
    int j  = t & 31;           // float4 lane
    if (e0 >= N_FINE) return;
    int e1 = e0 + 1;

    // Per-warp metadata for both edges, loaded by 4 lanes then broadcast.
    int   sA = 0, dA = 0, sB = 0, dB = 0;
    float cA = 0.f, snA = 0.f, cB = 0.f, snB = 0.f;
    if (j == 0) sA = g_unpool_map[edge_src[e0]];
    if (j == 1) { dA = edge_dst[e0]; float2 v = conn[e0]; cA = v.x; snA = v.y; }
    if (j == 2) sB = g_unpool_map[edge_src[e1]];
    if (j == 3) { dB = edge_dst[e1]; float2 v = conn[e1]; cB = v.x; snB = v.y; }
    sA  = __shfl_sync(0xffffffffu, sA,  0);
    dA  = __shfl_sync(0xffffffffu, dA,  1);
    cA  = __shfl_sync(0xffffffffu, cA,  1);
    snA = __shfl_sync(0xffffffffu, snA, 1);
    sB  = __shfl_sync(0xffffffffu, sB,  2);
    dB  = __shfl_sync(0xffffffffu, dB,  3);
    cB  = __shfl_sync(0xffffffffu, cB,  3);
    snB = __shfl_sync(0xffffffffu, snB, 3);

    const float4* xa = x + (size_t)sA * ROW_F4;
    const float4* xb = x + (size_t)sB * ROW_F4;

    // 8 independent loads, issued before any dependent compute.
    float4 a0 = __ldg(xa + j);
    float4 a1 = __ldg(xa + j + 32);
    float4 a2 = __ldg(xa + j + 64);
    float4 a3 = __ldg(xa + j + 96);
    float4 b0 = __ldg(xb + j);
    float4 b1 = __ldg(xb + j + 32);
    float4 b2 = __ldg(xb + j + 64);
    float4 b3 = __ldg(xb + j + 96);

    // (re + i*im) * (c - i*s) for group-1 chunks of both rows.
    float4 ra2, ra3, rb2, rb3;
    ra2.x = fmaf(a2.x, cA,  a2.y * snA);
    ra2.y = fmaf(a2.y, cA, -a2.x * snA);
    ra2.z = fmaf(a2.z, cA,  a2.w * snA);
    ra2.w = fmaf(a2.w, cA, -a2.z * snA);
    ra3.x = fmaf(a3.x, cA,  a3.y * snA);
    ra3.y = fmaf(a3.y, cA, -a3.x * snA);
    ra3.z = fmaf(a3.z, cA,  a3.w * snA);
    ra3.w = fmaf(a3.w, cA, -a3.z * snA);
    rb2.x = fmaf(b2.x, cB,  b2.y * snB);
    rb2.y = fmaf(b2.y, cB, -b2.x * snB);
    rb2.z = fmaf(b2.z, cB,  b2.w * snB);
    rb2.w = fmaf(b2.w, cB, -b2.z * snB);
    rb3.x = fmaf(b3.x, cB,  b3.y * snB);
    rb3.y = fmaf(b3.y, cB, -b3.x * snB);
    rb3.z = fmaf(b3.z, cB,  b3.w * snB);
    rb3.w = fmaf(b3.w, cB, -b3.z * snB);

    float4* oa = out + (size_t)dA * ROW_F4;
    float4* ob = out + (size_t)dB * ROW_F4;
    __stcs(oa + j,      a0);
    __stcs(oa + j + 32, a1);
    __stcs(oa + j + 64, ra2);
    __stcs(oa + j + 96, ra3);
    __stcs(ob + j,      b0);
    __stcs(ob + j + 32, b1);
    __stcs(ob + j + 64, rb2);
    __stcs(ob + j + 96, rb3);
}

extern "C" void kernel_launch(void* const* d_in, const int* in_sizes, int n_in,
                              void* d_out, int out_size) {
    // metadata order: x, unpool_connection, unpool_nodes, unpool_edges, num_nodes
    const float4* x     = (const float4*)d_in[0];
    const float2* conn  = (const float2*)d_in[1];
    const int*    nodes = (const int*)d_in[2];
    const int*    edges = (const int*)d_in[3];   // [2, N_FINE]: row0=src, row1=dst
    float4*       out   = (float4*)d_out;

    (void)in_sizes; (void)n_in; (void)out_size;

    build_map_kernel<<<(N_COARSE + 255) / 256, 256>>>(nodes);

    // 2 edges per warp -> N_FINE/2 warps -> 16 edges per 256-thread block.
    const int blocks = (N_FINE / 2 * 32 + 255) / 256;   // 12500
    unpool_kernel<<<blocks, 256>>>(x, conn, edges, edges + N_FINE, out);
}